// round 2
// baseline (speedup 1.0000x reference)
#include <cuda_runtime.h>
#include <cstdint>

// ---------------- problem dims ----------------
#define T_DIM 8192
#define D_DIM 1024
#define H_DIM 4096

// scratch (device globals: no allocation allowed)
__device__ float g_h  [(size_t)T_DIM * H_DIM];   // 128 MB intermediate
__device__ float g_xr [(size_t)T_DIM * D_DIM];   // tf32-rounded x
__device__ float g_wfc[(size_t)H_DIM * D_DIM];   // tf32-rounded W_fc
__device__ float g_wpr[(size_t)D_DIM * H_DIM];   // tf32-rounded W_proj

// ---------------- helpers ----------------
__device__ __forceinline__ uint32_t smem_u32(const void* p) {
    uint32_t a;
    asm("{ .reg .u64 t; cvta.to.shared.u64 t, %1; cvt.u32.u64 %0, t; }" : "=r"(a) : "l"(p));
    return a;
}
__device__ __forceinline__ uint32_t swz(uint32_t b) {   // SW128: XOR bits[6:4] with bits[9:7]
    return b ^ ((b >> 3) & 0x70u);
}
__device__ __forceinline__ void cp_async16(uint32_t saddr, const void* g) {
    asm volatile("cp.async.cg.shared.global [%0], [%1], 16;" :: "r"(saddr), "l"(g));
}
#define CP_COMMIT() asm volatile("cp.async.commit_group;" ::: "memory")
#define CP_WAIT2()  asm volatile("cp.async.wait_group 2;" ::: "memory")

#define LDSM_X4(r0, r1, r2, r3, addr) \
    asm volatile("ldmatrix.sync.aligned.m8n8.x4.shared.b16 {%0,%1,%2,%3}, [%4];" \
        : "=r"(r0), "=r"(r1), "=r"(r2), "=r"(r3) : "r"(addr))

#define MMA_TF32(c0, c1, c2, c3, a0, a1, a2, a3, b0, b1) \
    asm volatile("mma.sync.aligned.m16n8k8.row.col.f32.tf32.tf32.f32 " \
        "{%0,%1,%2,%3}, {%4,%5,%6,%7}, {%8,%9}, {%0,%1,%2,%3};" \
        : "+f"(c0), "+f"(c1), "+f"(c2), "+f"(c3) \
        : "r"(a0), "r"(a1), "r"(a2), "r"(a3), "r"(b0), "r"(b1))

// ---------------- GEMM config ----------------
static constexpr int BLK_M = 128;
static constexpr int BLK_N = 128;
static constexpr int BLK_K = 32;                 // 128 bytes per row
static constexpr int STAGES = 4;
static constexpr int A_BYTES = BLK_M * BLK_K * 4;          // 16384
static constexpr int B_BYTES = BLK_N * BLK_K * 4;          // 16384
static constexpr int STAGE_BYTES = A_BYTES + B_BYTES;      // 32768
static constexpr int SMEM_TOTAL = STAGES * STAGE_BYTES;    // 131072

// load one 128x32 A tile + 128x32 B tile into stage `st`
__device__ __forceinline__ void load_tile(uint32_t sBase, const float* __restrict__ gA,
                                          const float* __restrict__ gB, int K, int kt, int tid)
{
    const int k0 = kt * BLK_K;
    #pragma unroll
    for (int i = 0; i < 4; ++i) {                  // A: 1024 x 16B chunks / 256 thr
        int chunk = tid + i * 256;
        int row = chunk >> 3, unit = chunk & 7;
        uint32_t off = row * 128 + unit * 16;
        cp_async16(sBase + swz(off), gA + (size_t)row * K + k0 + unit * 4);
    }
    #pragma unroll
    for (int i = 0; i < 4; ++i) {                  // B
        int chunk = tid + i * 256;
        int row = chunk >> 3, unit = chunk & 7;
        uint32_t off = row * 128 + unit * 16;
        cp_async16(sBase + A_BYTES + swz(off), gB + (size_t)row * K + k0 + unit * 4);
    }
}

template <bool RELU2>
__global__ void __launch_bounds__(256, 1) gemm_tf32_mma(
    const float* __restrict__ A,   // [M, K] row-major (K contiguous)
    const float* __restrict__ B,   // [N, K] row-major (K contiguous)
    float* __restrict__ C,         // [M, N]
    int K, int ldc)
{
    extern __shared__ char smem[];
    const uint32_t sb = smem_u32(smem);
    const int tid  = threadIdx.x;
    const int lane = tid & 31;
    const int warp = tid >> 5;
    const int wm = (warp & 3) * 32;        // warp grid 4x2, warp tile 32x64
    const int wn = (warp >> 2) * 64;

    const float* gA = A + (size_t)blockIdx.x * BLK_M * K;
    const float* gB = B + (size_t)blockIdx.y * BLK_N * K;
    const int KT = K / BLK_K;

    // prologue: 3 stages in flight
    #pragma unroll
    for (int p = 0; p < 3; ++p) {
        load_tile(sb + p * STAGE_BYTES, gA, gB, K, p, tid);
        CP_COMMIT();
    }

    // ldmatrix address precompute (within-tile linear offsets; swizzle applied per step)
    const uint32_t xmask = (uint32_t)(lane & 7) << 4;
    const uint32_t aLin0 = (uint32_t)(wm + (lane & 15)) * 128 + (uint32_t)(lane >> 4) * 16;
    const uint32_t aLin1 = aLin0 + 16 * 128;
    uint32_t bLin[4];
    #pragma unroll
    for (int jp = 0; jp < 4; ++jp)
        bLin[jp] = (uint32_t)(wn + jp * 16 + (lane & 15)) * 128 + (uint32_t)(lane >> 4) * 16;

    float c[2][8][4];
    #pragma unroll
    for (int mi = 0; mi < 2; ++mi)
        #pragma unroll
        for (int j = 0; j < 8; ++j)
            #pragma unroll
            for (int q = 0; q < 4; ++q) c[mi][j][q] = 0.0f;

    for (int kt = 0; kt < KT; ++kt) {
        CP_WAIT2();
        __syncthreads();

        // prefetch stage kt+3 (overlaps with compute below)
        int nk = kt + 3;
        if (nk < KT) load_tile(sb + (nk & 3) * STAGE_BYTES, gA, gB, K, nk, tid);
        CP_COMMIT();

        const uint32_t st = sb + (kt & 3) * STAGE_BYTES;
        #pragma unroll
        for (int s = 0; s < 4; ++s) {              // 4 x K=8 steps
            const uint32_t add = s * 32;
            uint32_t a[2][4], b[4][4];
            LDSM_X4(a[0][0], a[0][1], a[0][2], a[0][3], st + ((aLin0 + add) ^ xmask));
            LDSM_X4(a[1][0], a[1][1], a[1][2], a[1][3], st + ((aLin1 + add) ^ xmask));
            #pragma unroll
            for (int jp = 0; jp < 4; ++jp)
                LDSM_X4(b[jp][0], b[jp][1], b[jp][2], b[jp][3],
                        st + A_BYTES + ((bLin[jp] + add) ^ xmask));
            #pragma unroll
            for (int mi = 0; mi < 2; ++mi)
                #pragma unroll
                for (int jp = 0; jp < 4; ++jp) {
                    MMA_TF32(c[mi][2 * jp][0], c[mi][2 * jp][1], c[mi][2 * jp][2], c[mi][2 * jp][3],
                             a[mi][0], a[mi][1], a[mi][2], a[mi][3], b[jp][0], b[jp][2]);
                    MMA_TF32(c[mi][2 * jp + 1][0], c[mi][2 * jp + 1][1], c[mi][2 * jp + 1][2], c[mi][2 * jp + 1][3],
                             a[mi][0], a[mi][1], a[mi][2], a[mi][3], b[jp][1], b[jp][3]);
                }
        }
    }

    // epilogue: direct STG.64, fragment layout d0..d3
    const int row0 = blockIdx.x * BLK_M + wm + (lane >> 2);
    const int col0 = blockIdx.y * BLK_N + wn + (lane & 3) * 2;
    #pragma unroll
    for (int mi = 0; mi < 2; ++mi)
        #pragma unroll
        for (int rr = 0; rr < 2; ++rr) {
            const int row = row0 + mi * 16 + rr * 8;
            float* base = C + (size_t)row * ldc + col0;
            #pragma unroll
            for (int j = 0; j < 8; ++j) {
                float v0 = c[mi][j][rr * 2], v1 = c[mi][j][rr * 2 + 1];
                if (RELU2) {
                    v0 = fmaxf(v0, 0.0f); v0 *= v0;
                    v1 = fmaxf(v1, 0.0f); v1 *= v1;
                    uint32_t u0, u1;
                    asm("cvt.rna.tf32.f32 %0, %1;" : "=r"(u0) : "f"(v0));
                    asm("cvt.rna.tf32.f32 %0, %1;" : "=r"(u1) : "f"(v1));
                    v0 = __uint_as_float(u0); v1 = __uint_as_float(u1);
                }
                *reinterpret_cast<float2*>(base + j * 8) = make_float2(v0, v1);
            }
        }
}

// ---------------- tf32 round-to-nearest pre-pass ----------------
__global__ void round_tf32_kernel(const float4* __restrict__ in, uint4* __restrict__ out, int n4)
{
    int i = blockIdx.x * blockDim.x + threadIdx.x;
    if (i >= n4) return;
    float4 v = in[i];
    uint4 o;
    asm("cvt.rna.tf32.f32 %0, %1;" : "=r"(o.x) : "f"(v.x));
    asm("cvt.rna.tf32.f32 %0, %1;" : "=r"(o.y) : "f"(v.y));
    asm("cvt.rna.tf32.f32 %0, %1;" : "=r"(o.z) : "f"(v.z));
    asm("cvt.rna.tf32.f32 %0, %1;" : "=r"(o.w) : "f"(v.w));
    out[i] = o;
}

// ---------------- host side ----------------
extern "C" void kernel_launch(void* const* d_in, const int* in_sizes, int n_in,
                              void* d_out, int out_size)
{
    const float* x   = (const float*)d_in[0];  // [8192, 1024]
    const float* wfc = (const float*)d_in[1];  // [4096, 1024]
    const float* wpr = (const float*)d_in[2];  // [1024, 4096]
    float* out = (float*)d_out;                // [8192, 1024]

    float *h, *xr, *wfcr, *wprr;
    cudaGetSymbolAddress((void**)&h,    g_h);
    cudaGetSymbolAddress((void**)&xr,   g_xr);
    cudaGetSymbolAddress((void**)&wfcr, g_wfc);
    cudaGetSymbolAddress((void**)&wprr, g_wpr);

    cudaFuncSetAttribute(gemm_tf32_mma<true>,
                         cudaFuncAttributeMaxDynamicSharedMemorySize, SMEM_TOTAL);
    cudaFuncSetAttribute(gemm_tf32_mma<false>,
                         cudaFuncAttributeMaxDynamicSharedMemorySize, SMEM_TOTAL);

    // tf32 RN pre-rounding (truncation bias would exceed the 1e-3 budget)
    {
        int n4x = T_DIM * D_DIM / 4;
        int n4f = H_DIM * D_DIM / 4;
        int n4p = D_DIM * H_DIM / 4;
        round_tf32_kernel<<<(n4x + 255) / 256, 256>>>((const float4*)x,   (uint4*)xr,   n4x);
        round_tf32_kernel<<<(n4f + 255) / 256, 256>>>((const float4*)wfc, (uint4*)wfcr, n4f);
        round_tf32_kernel<<<(n4p + 255) / 256, 256>>>((const float4*)wpr, (uint4*)wprr, n4p);
    }

    // GEMM1: h = relu(x @ Wfc^T)^2   [8192, 4096], K = 1024
    gemm_tf32_mma<true><<<dim3(T_DIM / BLK_M, H_DIM / BLK_N), 256, SMEM_TOTAL>>>(
        xr, wfcr, h, D_DIM, H_DIM);

    // GEMM2: out = h @ Wpr^T         [8192, 1024], K = 4096
    gemm_tf32_mma<false><<<dim3(T_DIM / BLK_M, D_DIM / BLK_N), 256, SMEM_TOTAL>>>(
        h, wprr, out, H_DIM, D_DIM);
}

// round 3
// speedup vs baseline: 1.1890x; 1.1890x over previous
#include <cuda_runtime.h>
#include <cstdint>

// ---------------- problem dims ----------------
#define T_DIM 8192
#define D_DIM 1024
#define H_DIM 4096

// scratch (device globals: no allocation allowed)
__device__ float g_h  [(size_t)T_DIM * H_DIM];   // 128 MB intermediate
__device__ float g_xr [(size_t)T_DIM * D_DIM];   // tf32-rounded x
__device__ float g_wfc[(size_t)H_DIM * D_DIM];   // tf32-rounded W_fc
__device__ float g_wpr[(size_t)D_DIM * H_DIM];   // tf32-rounded W_proj

// ---------------- helpers ----------------
__device__ __forceinline__ uint32_t smem_u32(const void* p) {
    uint32_t a;
    asm("{ .reg .u64 t; cvta.to.shared.u64 t, %1; cvt.u32.u64 %0, t; }" : "=r"(a) : "l"(p));
    return a;
}
__device__ __forceinline__ uint32_t swz(uint32_t b) {   // SW128: XOR bits[6:4] with bits[9:7]
    return b ^ ((b >> 3) & 0x70u);
}
__device__ __forceinline__ void cp_async16(uint32_t saddr, const void* g) {
    asm volatile("cp.async.cg.shared.global [%0], [%1], 16;" :: "r"(saddr), "l"(g));
}
#define CP_COMMIT() asm volatile("cp.async.commit_group;" ::: "memory")
#define CP_WAIT1()  asm volatile("cp.async.wait_group 1;" ::: "memory")

#define LDSM_X4(r0, r1, r2, r3, addr) \
    asm volatile("ldmatrix.sync.aligned.m8n8.x4.shared.b16 {%0,%1,%2,%3}, [%4];" \
        : "=r"(r0), "=r"(r1), "=r"(r2), "=r"(r3) : "r"(addr))

#define MMA_TF32(c0, c1, c2, c3, a0, a1, a2, a3, b0, b1) \
    asm volatile("mma.sync.aligned.m16n8k8.row.col.f32.tf32.tf32.f32 " \
        "{%0,%1,%2,%3}, {%4,%5,%6,%7}, {%8,%9}, {%0,%1,%2,%3};" \
        : "+f"(c0), "+f"(c1), "+f"(c2), "+f"(c3) \
        : "r"(a0), "r"(a1), "r"(a2), "r"(a3), "r"(b0), "r"(b1))

// ---------------- GEMM config ----------------
static constexpr int BLK_M = 128;
static constexpr int BLK_N = 128;
static constexpr int BLK_K = 32;                 // 128 bytes per row
static constexpr int STAGES = 3;                 // 96KB -> 2 CTAs / SM
static constexpr int A_BYTES = BLK_M * BLK_K * 4;          // 16384
static constexpr int B_BYTES = BLK_N * BLK_K * 4;          // 16384
static constexpr int STAGE_BYTES = A_BYTES + B_BYTES;      // 32768
static constexpr int SMEM_TOTAL = STAGES * STAGE_BYTES;    // 98304

// load one 128x32 A tile + 128x32 B tile into stage at sBase
__device__ __forceinline__ void load_tile(uint32_t sBase, const float* __restrict__ gA,
                                          const float* __restrict__ gB, int K, int kt, int tid)
{
    const int k0 = kt * BLK_K;
    #pragma unroll
    for (int i = 0; i < 4; ++i) {                  // A: 1024 x 16B chunks / 256 thr
        int chunk = tid + i * 256;
        int row = chunk >> 3, unit = chunk & 7;
        uint32_t off = row * 128 + unit * 16;
        cp_async16(sBase + swz(off), gA + (size_t)row * K + k0 + unit * 4);
    }
    #pragma unroll
    for (int i = 0; i < 4; ++i) {                  // B
        int chunk = tid + i * 256;
        int row = chunk >> 3, unit = chunk & 7;
        uint32_t off = row * 128 + unit * 16;
        cp_async16(sBase + A_BYTES + swz(off), gB + (size_t)row * K + k0 + unit * 4);
    }
}

template <bool RELU2>
__global__ void __launch_bounds__(256, 2) gemm_tf32_mma(
    const float* __restrict__ A,   // [M, K] row-major (K contiguous)
    const float* __restrict__ B,   // [N, K] row-major (K contiguous)
    float* __restrict__ C,         // [M, N]
    int K, int ldc)
{
    extern __shared__ char smem[];
    const uint32_t sb = smem_u32(smem);
    const int tid  = threadIdx.x;
    const int lane = tid & 31;
    const int warp = tid >> 5;
    const int wm = (warp & 3) * 32;        // warp grid 4x2, warp tile 32x64
    const int wn = (warp >> 2) * 64;

    const float* gA = A + (size_t)blockIdx.x * BLK_M * K;
    const float* gB = B + (size_t)blockIdx.y * BLK_N * K;
    const int KT = K / BLK_K;

    // prologue: 2 stages in flight
    load_tile(sb, gA, gB, K, 0, tid);
    CP_COMMIT();
    load_tile(sb + STAGE_BYTES, gA, gB, K, 1, tid);
    CP_COMMIT();

    // ldmatrix address precompute (within-tile linear offsets; swizzle applied per step)
    const uint32_t xmask = (uint32_t)(lane & 7) << 4;
    const uint32_t aLin0 = (uint32_t)(wm + (lane & 15)) * 128 + (uint32_t)(lane >> 4) * 16;
    const uint32_t aLin1 = aLin0 + 16 * 128;
    uint32_t bLin[4];
    #pragma unroll
    for (int jp = 0; jp < 4; ++jp)
        bLin[jp] = (uint32_t)(wn + jp * 16 + (lane & 15)) * 128 + (uint32_t)(lane >> 4) * 16;

    float c[2][8][4];
    #pragma unroll
    for (int mi = 0; mi < 2; ++mi)
        #pragma unroll
        for (int j = 0; j < 8; ++j)
            #pragma unroll
            for (int q = 0; q < 4; ++q) c[mi][j][q] = 0.0f;

    int curSt = 0;   // stage being computed
    int pfSt  = 2;   // stage receiving prefetch (kt+2)
    for (int kt = 0; kt < KT; ++kt) {
        CP_WAIT1();
        __syncthreads();

        // prefetch stage kt+2 into the slot consumed at kt-1 (overlaps with compute)
        int nk = kt + 2;
        if (nk < KT) load_tile(sb + pfSt * STAGE_BYTES, gA, gB, K, nk, tid);
        CP_COMMIT();
        if (++pfSt == STAGES) pfSt = 0;

        const uint32_t st = sb + curSt * STAGE_BYTES;
        if (++curSt == STAGES) curSt = 0;

        #pragma unroll
        for (int s = 0; s < 4; ++s) {              // 4 x K=8 steps
            const uint32_t add = s * 32;
            uint32_t a[2][4], b[4][4];
            LDSM_X4(a[0][0], a[0][1], a[0][2], a[0][3], st + ((aLin0 + add) ^ xmask));
            LDSM_X4(a[1][0], a[1][1], a[1][2], a[1][3], st + ((aLin1 + add) ^ xmask));
            #pragma unroll
            for (int jp = 0; jp < 4; ++jp)
                LDSM_X4(b[jp][0], b[jp][1], b[jp][2], b[jp][3],
                        st + A_BYTES + ((bLin[jp] + add) ^ xmask));
            #pragma unroll
            for (int mi = 0; mi < 2; ++mi)
                #pragma unroll
                for (int jp = 0; jp < 4; ++jp) {
                    MMA_TF32(c[mi][2 * jp][0], c[mi][2 * jp][1], c[mi][2 * jp][2], c[mi][2 * jp][3],
                             a[mi][0], a[mi][1], a[mi][2], a[mi][3], b[jp][0], b[jp][2]);
                    MMA_TF32(c[mi][2 * jp + 1][0], c[mi][2 * jp + 1][1], c[mi][2 * jp + 1][2], c[mi][2 * jp + 1][3],
                             a[mi][0], a[mi][1], a[mi][2], a[mi][3], b[jp][1], b[jp][3]);
                }
        }
    }

    // epilogue: direct STG.64, fragment layout d0..d3
    const int row0 = blockIdx.x * BLK_M + wm + (lane >> 2);
    const int col0 = blockIdx.y * BLK_N + wn + (lane & 3) * 2;
    #pragma unroll
    for (int mi = 0; mi < 2; ++mi)
        #pragma unroll
        for (int rr = 0; rr < 2; ++rr) {
            const int row = row0 + mi * 16 + rr * 8;
            float* base = C + (size_t)row * ldc + col0;
            #pragma unroll
            for (int j = 0; j < 8; ++j) {
                float v0 = c[mi][j][rr * 2], v1 = c[mi][j][rr * 2 + 1];
                if (RELU2) {
                    v0 = fmaxf(v0, 0.0f); v0 *= v0;
                    v1 = fmaxf(v1, 0.0f); v1 *= v1;
                    uint32_t u0, u1;
                    asm("cvt.rna.tf32.f32 %0, %1;" : "=r"(u0) : "f"(v0));
                    asm("cvt.rna.tf32.f32 %0, %1;" : "=r"(u1) : "f"(v1));
                    v0 = __uint_as_float(u0); v1 = __uint_as_float(u1);
                }
                *reinterpret_cast<float2*>(base + j * 8) = make_float2(v0, v1);
            }
        }
}

// ---------------- tf32 round-to-nearest pre-pass ----------------
__global__ void round_tf32_kernel(const float4* __restrict__ in, uint4* __restrict__ out, int n4)
{
    int i = blockIdx.x * blockDim.x + threadIdx.x;
    if (i >= n4) return;
    float4 v = in[i];
    uint4 o;
    asm("cvt.rna.tf32.f32 %0, %1;" : "=r"(o.x) : "f"(v.x));
    asm("cvt.rna.tf32.f32 %0, %1;" : "=r"(o.y) : "f"(v.y));
    asm("cvt.rna.tf32.f32 %0, %1;" : "=r"(o.z) : "f"(v.z));
    asm("cvt.rna.tf32.f32 %0, %1;" : "=r"(o.w) : "f"(v.w));
    out[i] = o;
}

// ---------------- host side ----------------
extern "C" void kernel_launch(void* const* d_in, const int* in_sizes, int n_in,
                              void* d_out, int out_size)
{
    const float* x   = (const float*)d_in[0];  // [8192, 1024]
    const float* wfc = (const float*)d_in[1];  // [4096, 1024]
    const float* wpr = (const float*)d_in[2];  // [1024, 4096]
    float* out = (float*)d_out;                // [8192, 1024]

    float *h, *xr, *wfcr, *wprr;
    cudaGetSymbolAddress((void**)&h,    g_h);
    cudaGetSymbolAddress((void**)&xr,   g_xr);
    cudaGetSymbolAddress((void**)&wfcr, g_wfc);
    cudaGetSymbolAddress((void**)&wprr, g_wpr);

    cudaFuncSetAttribute(gemm_tf32_mma<true>,
                         cudaFuncAttributeMaxDynamicSharedMemorySize, SMEM_TOTAL);
    cudaFuncSetAttribute(gemm_tf32_mma<false>,
                         cudaFuncAttributeMaxDynamicSharedMemorySize, SMEM_TOTAL);

    // tf32 RN pre-rounding (truncation bias would exceed the 1e-3 budget)
    {
        int n4x = T_DIM * D_DIM / 4;
        int n4f = H_DIM * D_DIM / 4;
        int n4p = D_DIM * H_DIM / 4;
        round_tf32_kernel<<<(n4x + 255) / 256, 256>>>((const float4*)x,   (uint4*)xr,   n4x);
        round_tf32_kernel<<<(n4f + 255) / 256, 256>>>((const float4*)wfc, (uint4*)wfcr, n4f);
        round_tf32_kernel<<<(n4p + 255) / 256, 256>>>((const float4*)wpr, (uint4*)wprr, n4p);
    }

    // GEMM1: h = relu(x @ Wfc^T)^2   [8192, 4096], K = 1024
    gemm_tf32_mma<true><<<dim3(T_DIM / BLK_M, H_DIM / BLK_N), 256, SMEM_TOTAL>>>(
        xr, wfcr, h, D_DIM, H_DIM);

    // GEMM2: out = h @ Wpr^T         [8192, 1024], K = 4096
    gemm_tf32_mma<false><<<dim3(T_DIM / BLK_M, D_DIM / BLK_N), 256, SMEM_TOTAL>>>(
        h, wprr, out, H_DIM, D_DIM);
}